// round 9
// baseline (speedup 1.0000x reference)
#include <cuda_runtime.h>
#include <cuda_bf16.h>
#include <cstdint>

#define NROWS (256 * 32 * 32)   // 262144
#define D 64
#define K 1024
#define TILE_M 128
#define CHUNKC 256              // codes per smem chunk
#define NCHUNKC (K / CHUNKC)

// smem layout (dynamic): A 128x72 bf16 (144B rows) | B 256 codes x 144B | sqe 256 f32
#define SMA_BYTES (TILE_M * 144)
#define SMB_OFF   SMA_BYTES
#define SMB_BYTES (CHUNKC * 144)
#define SMQ_OFF   (SMB_OFF + SMB_BYTES)
#define SMEM_SZ   (SMQ_OFF + CHUNKC * 4)

__device__ float  g_embT[K * D];       // code-major codebook [k][d] fp32 (rescue/gather)
__device__ float  g_sqe[K];            // ||e_k||^2 exact fp32
__device__ unsigned g_Bpk[K * 32];     // bf16x2 codebook in mma-B-fragment order
__device__ float2 g_cand[NROWS * 8];   // per row: 4 lanes x top2 (score, idx-bits)
__device__ int    g_idx[NROWS];
__device__ double g_acc;

// ---------------- helpers ----------------
__device__ __forceinline__ unsigned bfbits(float f) {
    return (unsigned)__bfloat16_as_ushort(__float2bfloat16(f));
}
__device__ __forceinline__ uint32_t smem_u32(const void* p) {
    uint32_t a;
    asm("{ .reg .u64 t; cvta.to.shared.u64 t, %1; cvt.u32.u64 %0, t; }" : "=r"(a) : "l"(p));
    return a;
}
__device__ __forceinline__ void ldmat4(unsigned r[4], uint32_t saddr) {
    asm volatile("ldmatrix.sync.aligned.m8n8.x4.shared.b16 {%0,%1,%2,%3}, [%4];"
        : "=r"(r[0]), "=r"(r[1]), "=r"(r[2]), "=r"(r[3]) : "r"(saddr));
}
__device__ __forceinline__ void mma_bf16(float& d0, float& d1, float& d2, float& d3,
                                         const unsigned a[4], unsigned b0, unsigned b1) {
    asm volatile("mma.sync.aligned.m16n8k16.row.col.f32.bf16.bf16.f32 "
        "{%0,%1,%2,%3}, {%4,%5,%6,%7}, {%8,%9}, {%0,%1,%2,%3};"
        : "+f"(d0), "+f"(d1), "+f"(d2), "+f"(d3)
        : "r"(a[0]), "r"(a[1]), "r"(a[2]), "r"(a[3]), "r"(b0), "r"(b1));
}

// H1 bit-exact emulation of the reference arithmetic (identical to passing R7 path)
__device__ __forceinline__ int h1_emulate(const float* xv, int lo, int hi) {
    float l0 = 0.f, l1 = 0.f, l2 = 0.f, l3 = 0.f;
    #pragma unroll 4
    for (int d = 0; d < 64; d += 4) {
        l0 = fmaf(xv[d],     xv[d],     l0);
        l1 = fmaf(xv[d + 1], xv[d + 1], l1);
        l2 = fmaf(xv[d + 2], xv[d + 2], l2);
        l3 = fmaf(xv[d + 3], xv[d + 3], l3);
    }
    float A = (l0 + l1) + (l2 + l3);
    float Bl = 0.f, Bh = 0.f, dl = 0.f, dh = 0.f;
    #pragma unroll 8
    for (int d = 0; d < 64; d++) {
        float el = g_embT[lo * D + d], eh = g_embT[hi * D + d];
        Bl = fmaf(el, el, Bl);
        Bh = fmaf(eh, eh, Bh);
        dl = fmaf(xv[d], el, dl);
        dh = fmaf(xv[d], eh, dh);
    }
    float distlo = (A + Bl) - 2.0f * dl;
    float disthi = (A + Bh) - 2.0f * dh;
    return (disthi < distlo) ? hi : lo;   // strict '<': ties -> lower index
}

// ---------------- init: transpose, sqe, fragment-packed bf16 codebook ----------------
__global__ void vq_init_kernel(const float* __restrict__ emb) {
    int i = blockIdx.x * blockDim.x + threadIdx.x;   // 65536 threads
    if (i == 0) g_acc = 0.0;
    if (i < K * D) {
        int d = i >> 10;
        int k = i & (K - 1);
        g_embT[k * D + d] = emb[i];
    }
    if (i < K) {
        float s = 0.f;
        #pragma unroll 8
        for (int d = 0; d < D; d++) {
            float v = emb[d * K + i];
            s = fmaf(v, v, s);
        }
        g_sqe[i] = s;
    }
    if (i < K * 32) {
        // pair p covers dims (2p, 2p+1) of code c; B-frag position:
        // s = p/8 (kstep), rem = p%8, b = rem/4 (b0/b1), q = rem%4 (lane quad)
        int c = i >> 5, p = i & 31;
        float e0 = emb[(2 * p) * K + c], e1 = emb[(2 * p + 1) * K + c];
        unsigned v = bfbits(e0) | (bfbits(e1) << 16);
        int s = p >> 3, rem = p & 7, b = rem >> 2, q = rem & 3;
        g_Bpk[c * 32 + q * 8 + s * 2 + b] = v;
    }
}

// ---------------- coarse: bf16 mma.sync scores, per-lane top2 per row ----------------
__global__ void __launch_bounds__(128) vq_coarse(const float* __restrict__ x) {
    extern __shared__ char smem[];
    __nv_bfloat16* sA = (__nv_bfloat16*)smem;            // row stride 72 bf16 (144B)
    uint4* sB = (uint4*)(smem + SMB_OFF);                // code stride 9 uint4 (144B)
    float* sSq = (float*)(smem + SMQ_OFF);

    int tid = threadIdx.x, w = tid >> 5, l = tid & 31, q = l & 3;
    int rowbase = blockIdx.x * TILE_M;

    // build A = bf16(-2x), 128 rows x 64 dims
    for (int it = tid; it < TILE_M * 32; it += 128) {
        int r = it >> 5, p = it & 31;
        float2 xv = ((const float2*)x)[(size_t)(rowbase + r) * 32 + p];
        unsigned v = bfbits(-2.f * xv.x) | (bfbits(-2.f * xv.y) << 16);
        *(unsigned*)((char*)smem + r * 144 + p * 4) = v;
    }
    __syncthreads();

    // A fragments: warp w owns rows [w*32, w*32+32) = 2 m-tiles; 4 ksteps each
    unsigned afr[2][4][4];
    {
        int rr = (l & 15), cc = (l >> 4) * 8;
        #pragma unroll
        for (int t = 0; t < 2; t++) {
            int R = w * 32 + t * 16 + rr;
            #pragma unroll
            for (int s = 0; s < 4; s++) {
                uint32_t ad = smem_u32((char*)smem + R * 144 + (cc + s * 16) * 2);
                ldmat4(afr[t][s], ad);
            }
        }
    }

    // per-lane top2 for 4 rows (slots: 2t + rowhalf)
    float ts[4][2];
    int   ti[4][2];
    #pragma unroll
    for (int m = 0; m < 4; m++) { ts[m][0] = 3e38f; ts[m][1] = 3e38f; ti[m][0] = 0; ti[m][1] = 0; }

    for (int ch = 0; ch < NCHUNKC; ch++) {
        __syncthreads();
        const uint4* gB = ((const uint4*)g_Bpk) + ch * CHUNKC * 8;
        for (int j = tid; j < CHUNKC * 8; j += 128)
            sB[(j >> 3) * 9 + (j & 7)] = gB[j];
        for (int j = tid; j < CHUNKC; j += 128)
            sSq[j] = g_sqe[ch * CHUNKC + j];
        __syncthreads();

        int c0 = ch * CHUNKC;
        for (int nt = 0; nt < CHUNKC / 8; nt++) {
            int codeb = nt * 8 + (l >> 2);
            uint4 v0 = sB[codeb * 9 + q * 2];
            uint4 v1 = sB[codeb * 9 + q * 2 + 1];
            float2 sq = *(float2*)&sSq[nt * 8 + 2 * q];
            int ce = c0 + nt * 8 + 2 * q, co = ce + 1;
            #pragma unroll
            for (int t = 0; t < 2; t++) {
                float d0 = 0.f, d1 = 0.f, d2 = 0.f, d3 = 0.f;
                mma_bf16(d0, d1, d2, d3, afr[t][0], v0.x, v0.y);
                mma_bf16(d0, d1, d2, d3, afr[t][1], v0.z, v0.w);
                mma_bf16(d0, d1, d2, d3, afr[t][2], v1.x, v1.y);
                mma_bf16(d0, d1, d2, d3, afr[t][3], v1.z, v1.w);
                float va = d0 + sq.x, vb = d1 + sq.y;   // row l/4 (+t*16)
                float vc = d2 + sq.x, vd = d3 + sq.y;   // row l/4+8 (+t*16)
                int m0 = 2 * t, m1 = 2 * t + 1;
                // strict '<' with ascending codes => first-index tie-break
                if (va < ts[m0][1]) { if (va < ts[m0][0]) { ts[m0][1] = ts[m0][0]; ti[m0][1] = ti[m0][0]; ts[m0][0] = va; ti[m0][0] = ce; } else { ts[m0][1] = va; ti[m0][1] = ce; } }
                if (vb < ts[m0][1]) { if (vb < ts[m0][0]) { ts[m0][1] = ts[m0][0]; ti[m0][1] = ti[m0][0]; ts[m0][0] = vb; ti[m0][0] = co; } else { ts[m0][1] = vb; ti[m0][1] = co; } }
                if (vc < ts[m1][1]) { if (vc < ts[m1][0]) { ts[m1][1] = ts[m1][0]; ti[m1][1] = ti[m1][0]; ts[m1][0] = vc; ti[m1][0] = ce; } else { ts[m1][1] = vc; ti[m1][1] = ce; } }
                if (vd < ts[m1][1]) { if (vd < ts[m1][0]) { ts[m1][1] = ts[m1][0]; ti[m1][1] = ti[m1][0]; ts[m1][0] = vd; ti[m1][0] = co; } else { ts[m1][1] = vd; ti[m1][1] = co; } }
            }
        }
    }

    // write 4-lane x top2 candidates per row
    #pragma unroll
    for (int m = 0; m < 4; m++) {
        int grow = rowbase + w * 32 + (m & 1) * 8 + (m >> 1) * 16 + (l >> 2);
        g_cand[grow * 8 + q * 2 + 0] = make_float2(ts[m][0], __int_as_float(ti[m][0]));
        g_cand[grow * 8 + q * 2 + 1] = make_float2(ts[m][1], __int_as_float(ti[m][1]));
    }
}

// ---------------- rescue: merge 8 candidates, exact rescore, H1 emulation ----------------
__global__ void __launch_bounds__(128) vq_rescue_kernel(const float* __restrict__ x) {
    int row = blockIdx.x * 128 + threadIdx.x;
    float2 c[8];
    #pragma unroll
    for (int j = 0; j < 8; j++) c[j] = g_cand[row * 8 + j];
    // insertion sort ascending by (score, then code) — lower code wins ties
    #pragma unroll
    for (int a = 1; a < 8; a++) {
        float2 v = c[a];
        int b = a;
        while (b > 0 && (c[b - 1].x > v.x ||
               (c[b - 1].x == v.x && __float_as_int(c[b - 1].y) > __float_as_int(v.y)))) {
            c[b] = c[b - 1]; b--;
        }
        c[b] = v;
    }

    int winner;
    if (c[1].x - c[0].x >= 1e-2f && c[3].x - c[0].x >= 4e-3f) {
        winner = __float_as_int(c[0].y);   // coarse gap >> noise: certain, no emu band
    } else {
        float xv[64];
        const float4* xp = (const float4*)(x + (size_t)row * D);
        #pragma unroll
        for (int i = 0; i < 16; i++) {
            float4 v = xp[i];
            xv[4 * i] = v.x; xv[4 * i + 1] = v.y; xv[4 * i + 2] = v.z; xv[4 * i + 3] = v.w;
        }
        float b0 = 3e38f, b1 = 3e38f;
        int i0 = 0, i1 = 0;
        if (c[3].x - c[0].x < 4e-3f) {
            // clustered: full exact scan, ascending codes, strict '<'
            for (int k = 0; k < K; k++) {
                const float* e = &g_embT[k * D];
                float dot = 0.f;
                #pragma unroll 8
                for (int d = 0; d < D; d++) dot = fmaf(xv[d], e[d], dot);
                float val = fmaf(dot, -2.f, g_sqe[k]);
                if (val < b0)      { b1 = b0; i1 = i0; b0 = val; i0 = k; }
                else if (val < b1) { b1 = val; i1 = k; }
            }
        } else {
            // exact rescore of merged top-4, in ascending code order (tie semantics)
            int ids[4] = { __float_as_int(c[0].y), __float_as_int(c[1].y),
                           __float_as_int(c[2].y), __float_as_int(c[3].y) };
            #pragma unroll
            for (int a = 1; a < 4; a++) {
                int v = ids[a], b = a;
                while (b > 0 && ids[b - 1] > v) { ids[b] = ids[b - 1]; b--; }
                ids[b] = v;
            }
            #pragma unroll
            for (int j = 0; j < 4; j++) {
                const float* e = &g_embT[ids[j] * D];
                float dot = 0.f;
                #pragma unroll 8
                for (int d = 0; d < D; d++) dot = fmaf(xv[d], e[d], dot);
                float val = fmaf(dot, -2.f, g_sqe[ids[j]]);
                if (val < b0)      { b1 = b0; i1 = i0; b0 = val; i0 = ids[j]; }
                else if (val < b1) { b1 = val; i1 = ids[j]; }
            }
        }
        winner = (b1 - b0 < 1e-3f) ? h1_emulate(xv, min(i0, i1), max(i0, i1)) : i0;
    }
    g_idx[row] = winner;
}

// ---------------- gather + loss (unchanged from passing kernel) ----------------
__global__ void vq_gather_kernel(const float* __restrict__ x, float* __restrict__ out) {
    __shared__ double sred[8];
    const long total = (long)NROWS * D / 4;
    double local = 0.0;
    for (long j = (long)blockIdx.x * blockDim.x + threadIdx.x; j < total;
         j += (long)gridDim.x * blockDim.x) {
        long i = j * 4;
        int row = (int)(i >> 6);
        int d   = (int)(i & 63);
        int idx = g_idx[row];
        float4 qv = *reinterpret_cast<const float4*>(&g_embT[idx * D + d]);
        float4 xv = *reinterpret_cast<const float4*>(x + i);
        float d0 = qv.x - xv.x, d1 = qv.y - xv.y, d2 = qv.z - xv.z, d3 = qv.w - xv.w;
        float4 o;
        o.x = xv.x + d0; o.y = xv.y + d1; o.z = xv.z + d2; o.w = xv.w + d3;
        *reinterpret_cast<float4*>(out + i) = o;
        local += (double)d0 * d0 + (double)d1 * d1 + (double)d2 * d2 + (double)d3 * d3;
    }
    #pragma unroll
    for (int off = 16; off > 0; off >>= 1)
        local += __shfl_down_sync(0xffffffffu, local, off);
    int wid = threadIdx.x >> 5, lid = threadIdx.x & 31;
    if (lid == 0) sred[wid] = local;
    __syncthreads();
    if (threadIdx.x == 0) {
        double s = 0.0;
        #pragma unroll
        for (int w = 0; w < 8; w++) s += sred[w];
        atomicAdd(&g_acc, s);
    }
}

__global__ void vq_finalize_kernel(float* __restrict__ loss_out) {
    double m = g_acc / (double)((long)NROWS * D);
    float lf = (float)m;
    *loss_out = 0.25f * lf + lf;
}

extern "C" void kernel_launch(void* const* d_in, const int* in_sizes, int n_in,
                              void* d_out, int out_size) {
    const float* x   = (const float*)d_in[0];   // [256,32,32,64] fp32
    const float* emb = (const float*)d_in[1];   // [64,1024] fp32
    float* out = (float*)d_out;

    cudaFuncSetAttribute(vq_coarse, cudaFuncAttributeMaxDynamicSharedMemorySize, SMEM_SZ);

    vq_init_kernel<<<256, 256>>>(emb);
    vq_coarse<<<NROWS / TILE_M, 128, SMEM_SZ>>>(x);
    vq_rescue_kernel<<<NROWS / 128, 128>>>(x);
    vq_gather_kernel<<<2048, 256>>>(x, out);
    vq_finalize_kernel<<<1, 1>>>(out + (out_size - 1));
}